// round 5
// baseline (speedup 1.0000x reference)
#include <cuda_runtime.h>

// Appro_WAConv2d: depthwise 7x7 conv with mantissa-approximation factor.
//   term = x*w*(f1+f2-1)/(f1*f2) = u*w + s*(w/f2),  u = x/f1, s = x - u
// Round-4 change: pack the two terms into one fma.rn.f32x2 per tap.
//   smem input  : interleaved float2 {u, s}   (natural 64-bit operand)
//   smem weight : float2 {w, w/f2}            (natural 64-bit operand)
//   acc         : packed f32x2; output = lane0 + lane1
// -> 49 FFMA2 per output instead of 98 FFMA, zero packing overhead.
// Tiling: 4x2 outputs/thread, 392 threads (28x14 tiles), 16B/lane smem
// stride (conflict-free LDS.128), row stride 66 float2 (bank-offsets the
// 4-row tile step).

#define B_   4
#define C_   192
#define H_   56
#define W_   56
#define K_   7
#define PAD_ 3
#define SMROWS 62          // 56 + 2*3 halo
#define SR    66           // smem row stride in float2 (528B: 4*SR*8 % 128 = 64)
#define NTHR  392

// mantissa map: a=|v|+1e-7; mant in [1,2); result in [0.75,1.5). Bit trick:
__device__ __forceinline__ float mant_map(float v) {
    float a = fabsf(v) + 1e-7f;
    unsigned b = __float_as_uint(a);
    unsigned m = b & 0x007FFFFFu;
    unsigned e = (m & 0x00400000u) ? 0x3F000000u : 0x3F800000u; // exp 126/127
    return __uint_as_float(m | e);
}

__device__ __forceinline__ unsigned long long fma2(unsigned long long a,
                                                   unsigned long long b,
                                                   unsigned long long c) {
    unsigned long long d;
    asm("fma.rn.f32x2 %0, %1, %2, %3;" : "=l"(d) : "l"(a), "l"(b), "l"(c));
    return d;
}

__global__ __launch_bounds__(NTHR, 3)
void waconv_kernel(const float* __restrict__ x,
                   const float* __restrict__ w,
                   float* __restrict__ out) {
    __shared__ __align__(16) float2 sm[SMROWS * SR];   // {u, s} interleaved
    __shared__ __align__(8)  float2 sw[K_ * K_];       // {w, w/f2}

    const int plane = blockIdx.x;          // b*C + c
    const int c = plane % C_;
    const float* __restrict__ xp = x + (size_t)plane * (H_ * W_);
    const int tid = threadIdx.x;

    // ---- phase 1a: per-channel packed weights ----
    if (tid < K_ * K_) {
        float wv = w[c * (K_ * K_) + tid];
        float f2 = mant_map(wv);
        sw[tid] = make_float2(wv, __fdividef(wv, f2));
    }
    // ---- phase 1b: halo load + mantissa split, interleaved store ----
    for (int idx = tid; idx < SMROWS * SMROWS; idx += NTHR) {
        int r = idx / SMROWS;
        int q = idx - r * SMROWS;
        int iy = r - PAD_;
        int ix = q - PAD_;
        float v = 0.0f;
        if ((unsigned)iy < H_ && (unsigned)ix < W_) v = xp[iy * W_ + ix];
        float f1 = mant_map(v);
        float u  = __fdividef(v, f1);
        sm[r * SR + q] = make_float2(u, v - u);
    }
    __syncthreads();

    // ---- phase 2: 4x2 output tile per thread (14 x 28 tiles) ----
    const int ty = tid / 28;               // 0..13
    const int tx = tid - ty * 28;          // 0..27
    const int y0 = ty * 4;
    const int x0 = tx * 2;

    const unsigned long long* __restrict__ swq = (const unsigned long long*)sw;

    unsigned long long acc[4][2];
#pragma unroll
    for (int a = 0; a < 4; ++a) { acc[a][0] = 0ull; acc[a][1] = 0ull; }

#pragma unroll
    for (int t = 0; t < 10; ++t) {         // input halo row = y0 + t
        const unsigned long long* pr =
            (const unsigned long long*)&sm[(y0 + t) * SR + x0]; // 16B aligned
        unsigned long long p[8];
        ((ulonglong2*)p)[0] = ((const ulonglong2*)pr)[0];
        ((ulonglong2*)p)[1] = ((const ulonglong2*)pr)[1];
        ((ulonglong2*)p)[2] = ((const ulonglong2*)pr)[2];
        ((ulonglong2*)p)[3] = ((const ulonglong2*)pr)[3];
#pragma unroll
        for (int i = 0; i < K_; ++i) {
            const int oy = t - i;          // compile-time after unroll
            if (oy < 0 || oy > 3) continue;
#pragma unroll
            for (int j = 0; j < K_; ++j) {
                unsigned long long wp = swq[i * K_ + j];
                acc[oy][0] = fma2(p[j],     wp, acc[oy][0]);
                acc[oy][1] = fma2(p[j + 1], wp, acc[oy][1]);
            }
        }
    }

    // ---- epilogue: lane0 + lane1, float2 stores ----
    float* op = out + (size_t)plane * (H_ * W_) + y0 * W_ + x0;
#pragma unroll
    for (int oy = 0; oy < 4; ++oy) {
        float2 r;
        {
            unsigned lo = (unsigned)(acc[oy][0]);
            unsigned hi = (unsigned)(acc[oy][0] >> 32);
            r.x = __uint_as_float(lo) + __uint_as_float(hi);
        }
        {
            unsigned lo = (unsigned)(acc[oy][1]);
            unsigned hi = (unsigned)(acc[oy][1] >> 32);
            r.y = __uint_as_float(lo) + __uint_as_float(hi);
        }
        *(float2*)(op + oy * W_) = r;
    }
}

extern "C" void kernel_launch(void* const* d_in, const int* in_sizes, int n_in,
                              void* d_out, int out_size) {
    const float* x  = (const float*)d_in[0];   // (4,192,56,56) f32
    const float* wt = (const float*)d_in[1];   // (192,1,7,7)  f32
    float* out = (float*)d_out;                // (4,192,56,56) f32
    (void)in_sizes; (void)n_in; (void)out_size;
    waconv_kernel<<<B_ * C_, NTHR>>>(x, wt, out);
}

// round 6
// speedup vs baseline: 2.0410x; 2.0410x over previous
#include <cuda_runtime.h>

// Appro_WAConv2d: depthwise 7x7 conv with mantissa-approximation factor.
//   term = x*w*(f1+f2-1)/(f1*f2) = u*w + s*(w/f2),  u = x/f1, s = x - u
// Packed formulation: smem holds interleaved {u,s} float2, weights {w, w/f2};
// each tap is one fma.rn.f32x2; output = lane0 + lane1 of the packed acc.
// Round-6 change: __launch_bounds__(392, 2) — round 5's occupancy-3 bound
// capped regs at 48, forcing the 16 aligned 64-bit pairs (p[8] + acc[4][2])
// to spill to local memory (DRAM 3.9% -> 38%). 83-reg budget removes spills.

#define B_   4
#define C_   192
#define H_   56
#define W_   56
#define K_   7
#define PAD_ 3
#define SMROWS 62          // 56 + 2*3 halo
#define SR    66           // smem row stride in float2 (528B)
#define NTHR  392

// mantissa map: a=|v|+1e-7; mant in [1,2); result in [0.75,1.5). Bit trick:
__device__ __forceinline__ float mant_map(float v) {
    float a = fabsf(v) + 1e-7f;
    unsigned b = __float_as_uint(a);
    unsigned m = b & 0x007FFFFFu;
    unsigned e = (m & 0x00400000u) ? 0x3F000000u : 0x3F800000u; // exp 126/127
    return __uint_as_float(m | e);
}

__device__ __forceinline__ unsigned long long fma2(unsigned long long a,
                                                   unsigned long long b,
                                                   unsigned long long c) {
    unsigned long long d;
    asm("fma.rn.f32x2 %0, %1, %2, %3;" : "=l"(d) : "l"(a), "l"(b), "l"(c));
    return d;
}

__global__ __launch_bounds__(NTHR, 2)
void waconv_kernel(const float* __restrict__ x,
                   const float* __restrict__ w,
                   float* __restrict__ out) {
    __shared__ __align__(16) float2 sm[SMROWS * SR];   // {u, s} interleaved
    __shared__ __align__(8)  float2 sw[K_ * K_];       // {w, w/f2}

    const int plane = blockIdx.x;          // b*C + c
    const int c = plane % C_;
    const float* __restrict__ xp = x + (size_t)plane * (H_ * W_);
    const int tid = threadIdx.x;

    // ---- phase 1a: per-channel packed weights ----
    if (tid < K_ * K_) {
        float wv = w[c * (K_ * K_) + tid];
        float f2 = mant_map(wv);
        sw[tid] = make_float2(wv, __fdividef(wv, f2));
    }
    // ---- phase 1b: halo load + mantissa split, interleaved store ----
    for (int idx = tid; idx < SMROWS * SMROWS; idx += NTHR) {
        int r = idx / SMROWS;
        int q = idx - r * SMROWS;
        int iy = r - PAD_;
        int ix = q - PAD_;
        float v = 0.0f;
        if ((unsigned)iy < H_ && (unsigned)ix < W_) v = xp[iy * W_ + ix];
        float f1 = mant_map(v);
        float u  = __fdividef(v, f1);
        sm[r * SR + q] = make_float2(u, v - u);
    }
    __syncthreads();

    // ---- phase 2: 4x2 output tile per thread (14 x 28 tiles) ----
    const int ty = tid / 28;               // 0..13
    const int tx = tid - ty * 28;          // 0..27
    const int y0 = ty * 4;
    const int x0 = tx * 2;                 // packed units -> 16B/lane stride

    const unsigned long long* __restrict__ swq = (const unsigned long long*)sw;

    unsigned long long acc[4][2];
#pragma unroll
    for (int a = 0; a < 4; ++a) { acc[a][0] = 0ull; acc[a][1] = 0ull; }

#pragma unroll
    for (int t = 0; t < 10; ++t) {         // input halo row = y0 + t
        const unsigned long long* pr =
            (const unsigned long long*)&sm[(y0 + t) * SR + x0]; // 16B aligned
        unsigned long long p[8];
        ((ulonglong2*)p)[0] = ((const ulonglong2*)pr)[0];
        ((ulonglong2*)p)[1] = ((const ulonglong2*)pr)[1];
        ((ulonglong2*)p)[2] = ((const ulonglong2*)pr)[2];
        ((ulonglong2*)p)[3] = ((const ulonglong2*)pr)[3];
#pragma unroll
        for (int i = 0; i < K_; ++i) {
            const int oy = t - i;          // compile-time after unroll
            if (oy < 0 || oy > 3) continue;
#pragma unroll
            for (int j = 0; j < K_; ++j) {
                unsigned long long wp = swq[i * K_ + j];
                acc[oy][0] = fma2(p[j],     wp, acc[oy][0]);
                acc[oy][1] = fma2(p[j + 1], wp, acc[oy][1]);
            }
        }
    }

    // ---- epilogue: lane0 + lane1, float2 stores ----
    float* op = out + (size_t)plane * (H_ * W_) + y0 * W_ + x0;
#pragma unroll
    for (int oy = 0; oy < 4; ++oy) {
        float2 r;
        {
            unsigned lo = (unsigned)(acc[oy][0]);
            unsigned hi = (unsigned)(acc[oy][0] >> 32);
            r.x = __uint_as_float(lo) + __uint_as_float(hi);
        }
        {
            unsigned lo = (unsigned)(acc[oy][1]);
            unsigned hi = (unsigned)(acc[oy][1] >> 32);
            r.y = __uint_as_float(lo) + __uint_as_float(hi);
        }
        *(float2*)(op + oy * W_) = r;
    }
}

extern "C" void kernel_launch(void* const* d_in, const int* in_sizes, int n_in,
                              void* d_out, int out_size) {
    const float* x  = (const float*)d_in[0];   // (4,192,56,56) f32
    const float* wt = (const float*)d_in[1];   // (192,1,7,7)  f32
    float* out = (float*)d_out;                // (4,192,56,56) f32
    (void)in_sizes; (void)n_in; (void)out_size;
    waconv_kernel<<<B_ * C_, NTHR>>>(x, wt, out);
}

// round 7
// speedup vs baseline: 2.0772x; 1.0177x over previous
#include <cuda_runtime.h>

// Appro_WAConv2d: depthwise 7x7 conv with mantissa-approximation factor.
//   term = x*w*(f1+f2-1)/(f1*f2) = u*w + s*(w/f2),  u = x/f1, s = x - u
// Packed f32x2 formulation: smem {u,s} float2, weights {w, w/f2};
// one fma.rn.f32x2 per tap; output = lane0 + lane1 of packed acc.
// Round-7: occupancy push. Half-plane blocks (grid 1536), 2x2 tile per
// thread -> ~40 regs, __launch_bounds__(392,3) => 39 warps/SM (61% occ,
// was 34%). Weight rows padded to 8 pairs, loaded as LDS.128 broadcasts.

#define B_   4
#define C_   192
#define H_   56
#define W_   56
#define K_   7
#define PAD_ 3
#define HR    28           // output rows per block (half plane)
#define SMROWS 34          // 28 + 2*3 halo rows
#define SMCOLS 62          // 56 + 2*3 halo cols
#define SR    66           // smem row stride in float2
#define NTHR  392

// mantissa map: a=|v|+1e-7; mant in [1,2); result in [0.75,1.5). Bit trick:
__device__ __forceinline__ float mant_map(float v) {
    float a = fabsf(v) + 1e-7f;
    unsigned b = __float_as_uint(a);
    unsigned m = b & 0x007FFFFFu;
    unsigned e = (m & 0x00400000u) ? 0x3F000000u : 0x3F800000u; // exp 126/127
    return __uint_as_float(m | e);
}

__device__ __forceinline__ unsigned long long fma2(unsigned long long a,
                                                   unsigned long long b,
                                                   unsigned long long c) {
    unsigned long long d;
    asm("fma.rn.f32x2 %0, %1, %2, %3;" : "=l"(d) : "l"(a), "l"(b), "l"(c));
    return d;
}

__device__ __forceinline__ float pairsum(unsigned long long v) {
    return __uint_as_float((unsigned)v) + __uint_as_float((unsigned)(v >> 32));
}

__global__ __launch_bounds__(NTHR, 3)
void waconv_kernel(const float* __restrict__ x,
                   const float* __restrict__ w,
                   float* __restrict__ out) {
    __shared__ __align__(16) float2 sm[SMROWS * SR];   // {u, s} interleaved
    __shared__ __align__(16) float2 sw[K_ * 8];        // {w, w/f2}, rows padded to 8

    const int bid   = blockIdx.x;
    const int plane = bid >> 1;            // b*C + c
    const int half  = bid & 1;
    const int h0    = half * HR;           // first output row of this block
    const int c     = plane % C_;
    const float* __restrict__ xp = x + (size_t)plane * (H_ * W_);
    const int tid = threadIdx.x;

    // ---- phase 1a: per-channel packed weights (rows padded to 8 pairs) ----
    if (tid < K_ * 8) {
        int j = tid & 7;
        float2 v = make_float2(0.0f, 0.0f);
        if (j < K_) {
            float wv = w[c * (K_ * K_) + (tid >> 3) * K_ + j];
            float f2 = mant_map(wv);
            v = make_float2(wv, __fdividef(wv, f2));
        }
        sw[tid] = v;
    }
    // ---- phase 1b: halo load + mantissa split, interleaved store ----
    for (int idx = tid; idx < SMROWS * SMCOLS; idx += NTHR) {
        int r = idx / SMCOLS;
        int q = idx - r * SMCOLS;
        int iy = h0 + r - PAD_;
        int ix = q - PAD_;
        float v = 0.0f;
        if ((unsigned)iy < H_ && (unsigned)ix < W_) v = xp[iy * W_ + ix];
        float f1 = mant_map(v);
        float u  = __fdividef(v, f1);
        sm[r * SR + q] = make_float2(u, v - u);
    }
    __syncthreads();

    // ---- phase 2: 2x2 output tile per thread (14 rows x 28 cols of tiles) ----
    const int ty = tid / 28;               // 0..13
    const int tx = tid - ty * 28;          // 0..27
    const int y0 = ty * 2;                 // local output row
    const int x0 = tx * 2;                 // output col (= packed smem col)

    const unsigned long long* __restrict__ swq = (const unsigned long long*)sw;

    unsigned long long acc00 = 0ull, acc01 = 0ull, acc10 = 0ull, acc11 = 0ull;

#pragma unroll
    for (int t = 0; t < 8; ++t) {          // input halo row = y0 + t
        const unsigned long long* pr =
            (const unsigned long long*)&sm[(y0 + t) * SR + x0]; // 16B aligned
        unsigned long long p[8];
        ((ulonglong2*)p)[0] = ((const ulonglong2*)pr)[0];
        ((ulonglong2*)p)[1] = ((const ulonglong2*)pr)[1];
        ((ulonglong2*)p)[2] = ((const ulonglong2*)pr)[2];
        ((ulonglong2*)p)[3] = ((const ulonglong2*)pr)[3];

        // oy = 0 uses kernel row i = t (valid t<=6)
        if (t <= 6) {
            const int i = t;
            unsigned long long ww[8];
            ((ulonglong2*)ww)[0] = ((const ulonglong2*)(swq + i * 8))[0];
            ((ulonglong2*)ww)[1] = ((const ulonglong2*)(swq + i * 8))[1];
            ((ulonglong2*)ww)[2] = ((const ulonglong2*)(swq + i * 8))[2];
            ((ulonglong2*)ww)[3] = ((const ulonglong2*)(swq + i * 8))[3];
#pragma unroll
            for (int j = 0; j < K_; ++j) {
                acc00 = fma2(p[j],     ww[j], acc00);
                acc01 = fma2(p[j + 1], ww[j], acc01);
            }
        }
        // oy = 1 uses kernel row i = t-1 (valid t>=1)
        if (t >= 1) {
            const int i = t - 1;
            unsigned long long ww[8];
            ((ulonglong2*)ww)[0] = ((const ulonglong2*)(swq + i * 8))[0];
            ((ulonglong2*)ww)[1] = ((const ulonglong2*)(swq + i * 8))[1];
            ((ulonglong2*)ww)[2] = ((const ulonglong2*)(swq + i * 8))[2];
            ((ulonglong2*)ww)[3] = ((const ulonglong2*)(swq + i * 8))[3];
#pragma unroll
            for (int j = 0; j < K_; ++j) {
                acc10 = fma2(p[j],     ww[j], acc10);
                acc11 = fma2(p[j + 1], ww[j], acc11);
            }
        }
    }

    // ---- epilogue: lane0 + lane1, float2 stores ----
    float* op = out + (size_t)plane * (H_ * W_) + (h0 + y0) * W_ + x0;
    *(float2*)(op)      = make_float2(pairsum(acc00), pairsum(acc01));
    *(float2*)(op + W_) = make_float2(pairsum(acc10), pairsum(acc11));
}

extern "C" void kernel_launch(void* const* d_in, const int* in_sizes, int n_in,
                              void* d_out, int out_size) {
    const float* x  = (const float*)d_in[0];   // (4,192,56,56) f32
    const float* wt = (const float*)d_in[1];   // (192,1,7,7)  f32
    float* out = (float*)d_out;                // (4,192,56,56) f32
    (void)in_sizes; (void)n_in; (void)out_size;
    waconv_kernel<<<B_ * C_ * 2, NTHR>>>(x, wt, out);
}